// round 1
// baseline (speedup 1.0000x reference)
#include <cuda_runtime.h>
#include <cstdint>

#define B_ 256
#define T_ 2048
#define I_ 50
#define H_ 116
#define O_ 50

typedef unsigned long long u64;

// Scratch for post-ReLU hidden states: [B, T, H] fp32 = 243 MB.
// (__device__ global array: allowed scratch; no runtime allocation.)
__device__ float g_hs[(size_t)B_ * T_ * H_];

// ---------------- packed f32x2 helpers (Blackwell) ----------------
__device__ __forceinline__ u64 fma2(u64 a, u64 b, u64 c) {
    u64 d;
    asm("fma.rn.f32x2 %0, %1, %2, %3;" : "=l"(d) : "l"(a), "l"(b), "l"(c));
    return d;
}
__device__ __forceinline__ u64 add2(u64 a, u64 b) {
    u64 d;
    asm("add.rn.f32x2 %0, %1, %2;" : "=l"(d) : "l"(a), "l"(b));
    return d;
}
__device__ __forceinline__ float pair_sum(u64 a) {
    float lo = __uint_as_float((unsigned)(a & 0xFFFFFFFFull));
    float hi = __uint_as_float((unsigned)(a >> 32));
    return lo + hi;
}
__device__ __forceinline__ void cp8(void* smem, const void* gmem) {
    unsigned s = (unsigned)__cvta_generic_to_shared(smem);
    asm volatile("cp.async.ca.shared.global [%0], [%1], 8;" :: "r"(s), "l"(gmem));
}

// ---------------- Kernel A: fused input-proj + ReLU recurrence ----------------
// 128 CTAs x 256 threads. CTA handles batch rows 2*blk and 2*blk+1.
// Threads [0,115] of each half compute h[j]; threads [116,127] prefetch x.
__global__ void __launch_bounds__(256, 1) rnn_kernel(
    const float* __restrict__ x,
    const float* __restrict__ W_ih,
    const float* __restrict__ b_ih,
    const float* __restrict__ W_hh,
    const float* __restrict__ b_hh)
{
    __shared__ __align__(16) float h_buf[2][2][128];   // [pingpong][row][j]
    __shared__ __align__(16) float x_buf[4][2][56];    // 4-slot ring, 50 used

    const int tid  = threadIdx.x;
    const int r    = tid >> 7;        // which batch row of the CTA
    const int lane = tid & 127;
    const int b    = blockIdx.x * 2 + r;
    const bool is_j = (lane < H_);
    const int j = lane;

    // Per-thread register-resident weight rows (as f32 pairs)
    u64 wih[25];
    u64 whh[58];
    float bias = 0.f;
    if (is_j) {
        const u64* p1 = reinterpret_cast<const u64*>(W_ih + j * I_);  // 8B aligned
        #pragma unroll
        for (int q = 0; q < 25; q++) wih[q] = p1[q];
        const u64* p2 = reinterpret_cast<const u64*>(W_hh + j * H_);  // 8B aligned
        #pragma unroll
        for (int q = 0; q < 58; q++) whh[q] = p2[q];
        bias = b_ih[j] + b_hh[j];
        h_buf[0][r][j] = 0.f;          // h0 = 0
    }

    const float* xb = x + (size_t)b * T_ * I_;
    const int u = lane - H_;           // loader index 0..11

    // Prologue: prefetch x for t = 0,1,2 (one cp.async group per timestep)
    if (!is_j) {
        #pragma unroll
        for (int s = 0; s < 3; s++) {
            cp8(&x_buf[s][r][2 * u],        xb + s * I_ + 2 * u);
            cp8(&x_buf[s][r][2 * (u + 12)], xb + s * I_ + 2 * (u + 12));
            if (u == 0) cp8(&x_buf[s][r][48], xb + s * I_ + 48);
            asm volatile("cp.async.commit_group;");
        }
        asm volatile("cp.async.wait_group 2;");  // slot 0 complete
    }
    __syncthreads();

    float* hs_ptr = g_hs + (size_t)b * T_ * H_ + j;
    int p = 0;
    for (int t = 0; t < T_; t++) {
        if (is_j) {
            u64 a0 = 0, a1 = 0, a2 = 0, a3 = 0;
            // input projection: xp[j] = sum_i W_ih[j,i] * x[b,t,i]
            const float* xrow = x_buf[t & 3][r];
            const ulonglong2* xv = reinterpret_cast<const ulonglong2*>(xrow);
            #pragma unroll
            for (int q = 0; q < 12; q++) {
                ulonglong2 v = xv[q];
                a0 = fma2(wih[2 * q],     v.x, a0);
                a1 = fma2(wih[2 * q + 1], v.y, a1);
            }
            a2 = fma2(wih[24], reinterpret_cast<const u64*>(xrow)[24], a2);
            // recurrence: + sum_k W_hh[j,k] * h[k]   (h broadcast from shared)
            const ulonglong2* hv =
                reinterpret_cast<const ulonglong2*>(h_buf[p][r]);
            #pragma unroll
            for (int q = 0; q < 29; q++) {
                ulonglong2 v = hv[q];
                if (q & 1) {
                    a2 = fma2(whh[2 * q],     v.x, a2);
                    a3 = fma2(whh[2 * q + 1], v.y, a3);
                } else {
                    a0 = fma2(whh[2 * q],     v.x, a0);
                    a1 = fma2(whh[2 * q + 1], v.y, a1);
                }
            }
            float h = pair_sum(add2(add2(a0, a1), add2(a2, a3))) + bias;
            h = fmaxf(h, 0.f);
            h_buf[p ^ 1][r][j] = h;
            hs_ptr[0] = h;             // coalesced 116-float row
            hs_ptr += H_;
        } else {
            // prefetch x for t+3 into slot (t+3)&3 (readers of that slot done)
            const int t3 = t + 3;
            if (t3 < T_) {
                cp8(&x_buf[t3 & 3][r][2 * u],        xb + t3 * I_ + 2 * u);
                cp8(&x_buf[t3 & 3][r][2 * (u + 12)], xb + t3 * I_ + 2 * (u + 12));
                if (u == 0) cp8(&x_buf[t3 & 3][r][48], xb + t3 * I_ + 48);
            }
            asm volatile("cp.async.commit_group;");
            asm volatile("cp.async.wait_group 2;");  // slot for t+1 complete
        }
        __syncthreads();
        p ^= 1;
    }
}

// ---------------- Kernel B: FC  out[n,o] = hs[n,:] . W_fc[o,:] + b_fc[o] ----
#define TILE_N 48
__global__ void __launch_bounds__(256, 2) fc_kernel(
    const float* __restrict__ W_fc,
    const float* __restrict__ b_fc,
    float* __restrict__ out)
{
    __shared__ __align__(16) float hs_s[TILE_N * H_];
    __shared__ __align__(16) float w_s[O_ * H_];
    __shared__ float bf_s[O_];

    const int tid = threadIdx.x;
    {   // load W_fc (23.2 KB) + bias once per block
        const float4* src = reinterpret_cast<const float4*>(W_fc);
        float4* dst = reinterpret_cast<float4*>(w_s);
        for (int i = tid; i < O_ * H_ / 4; i += 256) dst[i] = src[i];
        if (tid < O_) bf_s[tid] = b_fc[tid];
    }

    const float* hs = g_hs;
    const int NT = (B_ * T_ + TILE_N - 1) / TILE_N;   // 10923
    for (int tile = blockIdx.x; tile < NT; tile += gridDim.x) {
        const int n0 = tile * TILE_N;
        const int nrows = min(TILE_N, B_ * T_ - n0);
        __syncthreads();   // prior-tile readers done before overwrite
        if (nrows == TILE_N) {
            const float4* src =
                reinterpret_cast<const float4*>(hs + (size_t)n0 * H_);
            float4* dst = reinterpret_cast<float4*>(hs_s);
            #pragma unroll 4
            for (int i = tid; i < TILE_N * H_ / 4; i += 256) dst[i] = src[i];
        } else {
            for (int i = tid; i < nrows * H_; i += 256)
                hs_s[i] = hs[(size_t)n0 * H_ + i];
        }
        __syncthreads();
        for (int idx = tid; idx < nrows * O_; idx += 256) {
            const int n = idx / O_;
            const int o = idx - n * O_;
            const ulonglong2* hv =
                reinterpret_cast<const ulonglong2*>(hs_s + n * H_);
            const ulonglong2* wv =
                reinterpret_cast<const ulonglong2*>(w_s + o * H_);
            u64 a0 = 0, a1 = 0, a2 = 0, a3 = 0;
            #pragma unroll
            for (int q = 0; q < 29; q++) {
                ulonglong2 hvv = hv[q];
                ulonglong2 wvv = wv[q];
                if (q & 1) {
                    a2 = fma2(wvv.x, hvv.x, a2);
                    a3 = fma2(wvv.y, hvv.y, a3);
                } else {
                    a0 = fma2(wvv.x, hvv.x, a0);
                    a1 = fma2(wvv.y, hvv.y, a1);
                }
            }
            out[(size_t)(n0 + n) * O_ + o] =
                pair_sum(add2(add2(a0, a1), add2(a2, a3))) + bf_s[o];
        }
    }
}

// ---------------- launch ----------------
extern "C" void kernel_launch(void* const* d_in, const int* in_sizes, int n_in,
                              void* d_out, int out_size)
{
    const float* x    = (const float*)d_in[0];
    const float* W_ih = (const float*)d_in[1];
    const float* b_ih = (const float*)d_in[2];
    const float* W_hh = (const float*)d_in[3];
    const float* b_hh = (const float*)d_in[4];
    const float* W_fc = (const float*)d_in[5];
    const float* b_fc = (const float*)d_in[6];
    float* out = (float*)d_out;

    rnn_kernel<<<B_ / 2, 256>>>(x, W_ih, b_ih, W_hh, b_hh);
    fc_kernel<<<2048, 256>>>(W_fc, b_fc, out);
}